// round 15
// baseline (speedup 1.0000x reference)
#include <cuda_runtime.h>
#include <mma.h>
#include <math.h>
#include <cstdint>
#include <cuda_fp16.h>

using namespace nvcuda;

// BERT-base forward: B=4, S=512, L=12, D=768, H=12, F=3072, V=30522
#define Bq 4
#define Sq 512
#define Lq 12
#define Dq 768
#define Hq 12
#define Fq 3072
#define Vq 30522
#define HDq 64
#define Tq 2048    // B*S tokens
#define Npad 30592 // 239*128, padded vocab width

#define LDD ((size_t)Lq * Dq * Dq)
#define LDF ((size_t)Lq * Dq * Fq)

// fp32 workspace: x, x1 [T,D]; tmp32 [2][T,D]; bpad [Npad]
__device__ float g_ws[4 * (size_t)Tq * Dq + Npad];
// fp16 workspace: xH,x1H,qH,kH,vH,tbH [T,D]; hbH [T,F]; wpadH [D,Npad];
// hWq,hWk,hWv,hWo [L,D,D]; hF1 [L,D,F]; hF2 [L,F,D]
__device__ __half g_hws[6 * (size_t)Tq * Dq + (size_t)Tq * Fq
                        + (size_t)Dq * Npad + 4 * LDD + 2 * LDF];

__device__ __forceinline__ __half H16(float x) { return __float2half_rn(x); }

__device__ __forceinline__ void cp16(uint32_t dst, const void* src) {
    asm volatile("cp.async.cg.shared.global [%0], [%1], 16;" :: "r"(dst), "l"(src));
}
__device__ __forceinline__ void cp_commit() {
    asm volatile("cp.async.commit_group;");
}
template <int N>
__device__ __forceinline__ void cp_wait() {
    asm volatile("cp.async.wait_group %0;" :: "n"(N));
}
__device__ __forceinline__ uint32_t smem_u32(const void* p) {
    return (uint32_t)__cvta_generic_to_shared(p);
}

// ---------------------------------------------------------------------------
// Block-wide sum of (a,b) pairs, 256 threads
// ---------------------------------------------------------------------------
__device__ __forceinline__ float2 blockReduce2(float a, float b) {
#pragma unroll
    for (int o = 16; o > 0; o >>= 1) {
        a += __shfl_down_sync(0xffffffffu, a, o);
        b += __shfl_down_sync(0xffffffffu, b, o);
    }
    __shared__ float2 sh[8];
    int lane = threadIdx.x & 31, wid = threadIdx.x >> 5;
    if (lane == 0) sh[wid] = make_float2(a, b);
    __syncthreads();
    if (wid == 0) {
        float2 v = (lane < 8) ? sh[lane] : make_float2(0.f, 0.f);
#pragma unroll
        for (int o = 4; o > 0; o >>= 1) {
            v.x += __shfl_down_sync(0xffffffffu, v.x, o);
            v.y += __shfl_down_sync(0xffffffffu, v.y, o);
        }
        if (lane == 0) sh[0] = v;
    }
    __syncthreads();
    return sh[0];
}

// ---------------------------------------------------------------------------
// Embedding + LayerNorm: fp32 out + fp16-rounded copy
// ---------------------------------------------------------------------------
__global__ void embed_ln_kernel(const int* __restrict__ ids,
                                const float* __restrict__ wemb,
                                const float* __restrict__ pemb,
                                const float* __restrict__ semb,
                                const float* __restrict__ g,
                                const float* __restrict__ bta,
                                float* __restrict__ x,
                                __half* __restrict__ xH) {
    int t = blockIdx.x;
    int s = t & (Sq - 1);
    int id = ids[t];
    float v[3];
    float sum = 0.f, sq = 0.f;
#pragma unroll
    for (int i = 0; i < 3; i++) {
        int d = threadIdx.x + i * 256;
        float val = wemb[(size_t)id * Dq + d] + pemb[(size_t)s * Dq + d] + semb[d];
        v[i] = val;
        sum += val;
        sq += val * val;
    }
    float2 r = blockReduce2(sum, sq);
    float mu = r.x * (1.0f / Dq);
    float var = r.y * (1.0f / Dq) - mu * mu;
    float rstd = rsqrtf(var + 1e-5f);
#pragma unroll
    for (int i = 0; i < 3; i++) {
        int d = threadIdx.x + i * 256;
        float o = (v[i] - mu) * rstd * g[d] + bta[d];
        x[(size_t)t * Dq + d] = o;
        xH[(size_t)t * Dq + d] = H16(o);
    }
}

// ---------------------------------------------------------------------------
// out = LayerNorm(a + b0 + b1 + bias?): fp32 out + fp16 copy (split-K merge)
// ---------------------------------------------------------------------------
__global__ void add_ln3_kernel(const float* __restrict__ a,
                               const float* __restrict__ b0,
                               const float* __restrict__ b1,
                               const float* __restrict__ bias,
                               const float* __restrict__ g,
                               const float* __restrict__ bta,
                               float* __restrict__ out,
                               __half* __restrict__ outH) {
    int t = blockIdx.x;
    float v[3];
    float sum = 0.f, sq = 0.f;
#pragma unroll
    for (int i = 0; i < 3; i++) {
        int d = threadIdx.x + i * 256;
        size_t idx = (size_t)t * Dq + d;
        float val = a[idx] + b0[idx] + b1[idx];
        if (bias) val += bias[d];
        v[i] = val;
        sum += val;
        sq += val * val;
    }
    float2 r = blockReduce2(sum, sq);
    float mu = r.x * (1.0f / Dq);
    float var = r.y * (1.0f / Dq) - mu * mu;
    float rstd = rsqrtf(var + 1e-5f);
#pragma unroll
    for (int i = 0; i < 3; i++) {
        int d = threadIdx.x + i * 256;
        float o = (v[i] - mu) * rstd * g[d] + bta[d];
        out[(size_t)t * Dq + d] = o;
        outH[(size_t)t * Dq + d] = H16(o);
    }
}

// ---------------------------------------------------------------------------
// Elementwise fp32 -> fp16 (RNE), n multiple of 4
// ---------------------------------------------------------------------------
__global__ void cvt_half_kernel(const float* __restrict__ in,
                                __half* __restrict__ out, size_t n4) {
    size_t i = (size_t)blockIdx.x * 256 + threadIdx.x;
    if (i >= n4) return;
    float4 v = ((const float4*)in)[i];
    ((__half2*)out)[i * 2 + 0] = __floats2half2_rn(v.x, v.y);
    ((__half2*)out)[i * 2 + 1] = __floats2half2_rn(v.z, v.w);
}

__global__ void pad_vocab_kernel(const float* __restrict__ w,
                                 __half* __restrict__ wp) {
    size_t gid = (size_t)blockIdx.x * 256 + threadIdx.x;
    size_t i4 = gid * 4;
    if (i4 >= (size_t)Dq * Npad) return;
    int k = (int)(i4 / Npad);
    int c = (int)(i4 % Npad);
    float a = (c + 0 < Vq) ? w[(size_t)k * Vq + c + 0] : 0.f;
    float b = (c + 1 < Vq) ? w[(size_t)k * Vq + c + 1] : 0.f;
    float d = (c + 2 < Vq) ? w[(size_t)k * Vq + c + 2] : 0.f;
    float e = (c + 3 < Vq) ? w[(size_t)k * Vq + c + 3] : 0.f;
    ((__half2*)wp)[gid * 2 + 0] = __floats2half2_rn(a, b);
    ((__half2*)wp)[gid * 2 + 1] = __floats2half2_rn(d, e);
}

__global__ void pad_bias_kernel(const float* __restrict__ b,
                                float* __restrict__ bp) {
    int c = blockIdx.x * 256 + threadIdx.x;
    if (c < Npad) bp[c] = (c < Vq) ? b[c] : 0.f;
}

// ---------------------------------------------------------------------------
// FP16 WMMA GEMM, cp.async 4-stage: C[M,N] = A[M, kOff:kOff+Klen] @ B slice.
// 128x128 tile, BK=32, 8 warps (4 M x 2 N), warp tile 32x64, fp32 accum.
// MODE: 0 = float out, plain (direct frag store)
//       1 = float out, +bias (staged)
//       2 = half out, +bias + exact GELU (staged)
//       3 = half out, plain (staged)
// ---------------------------------------------------------------------------
#define AS_LD 40
#define BS_LD 136
#define STAGE_HALFS (128 * AS_LD + 32 * BS_LD)        // 9472
#define GEMM_SMEM_BYTES (4 * STAGE_HALFS * 2)         // 75776

template <int MODE>
__device__ __forceinline__ void gemm_body(const __half* __restrict__ A,
                                          const __half* __restrict__ Bt,
                                          const float* __restrict__ bias,
                                          void* __restrict__ Cv,
                                          int N, int Klen, int ldA, int ldB,
                                          int kOff) {
    extern __shared__ char smraw[];
    __half* smh = (__half*)smraw;
    float* smf = (float*)smraw;
    uint32_t smb = smem_u32(smraw);

    int tid = threadIdx.x;
    int row0 = blockIdx.y * 128, col0 = blockIdx.x * 128;
    int warp = tid >> 5, lane = tid & 31;
    int wm = warp & 3, wn = warp >> 2;

    wmma::fragment<wmma::accumulator, 16, 16, 16, float> acc[2][4];
#pragma unroll
    for (int i = 0; i < 2; i++)
#pragma unroll
        for (int j = 0; j < 4; j++)
            wmma::fill_fragment(acc[i][j], 0.0f);

    auto issue = [&](int i) {
        uint32_t sb = smb + (uint32_t)((i & 3) * STAGE_HALFS) * 2;
        uint32_t bb = sb + 128 * AS_LD * 2;
        int k0 = kOff + (i << 5);
#pragma unroll
        for (int it = 0; it < 2; it++) {
            int idx = tid + it * 256;
            int r = idx >> 2, c = idx & 3;
            cp16(sb + (uint32_t)((r * AS_LD + c * 8) * 2),
                 A + (size_t)(row0 + r) * ldA + k0 + c * 8);
        }
#pragma unroll
        for (int it = 0; it < 2; it++) {
            int idx = tid + it * 256;
            int r = idx >> 4, c = idx & 15;
            cp16(bb + (uint32_t)((r * BS_LD + c * 8) * 2),
                 Bt + (size_t)(k0 + r) * ldB + col0 + c * 8);
        }
        cp_commit();
    };

    int niter = Klen >> 5;
    issue(0);
    if (niter > 1) issue(1);
    if (niter > 2) issue(2);

    for (int i = 0; i < niter; i++) {
        if (i + 3 < niter) {
            issue(i + 3);
            cp_wait<3>();
        } else if (i + 2 < niter) {
            cp_wait<2>();
        } else if (i + 1 < niter) {
            cp_wait<1>();
        } else {
            cp_wait<0>();
        }
        __syncthreads();

        const __half* as = smh + (i & 3) * STAGE_HALFS;
        const __half* bs = as + 128 * AS_LD;
#pragma unroll
        for (int kk = 0; kk < 2; kk++) {
            wmma::fragment<wmma::matrix_a, 16, 16, 16, __half, wmma::row_major> af[2];
            wmma::fragment<wmma::matrix_b, 16, 16, 16, __half, wmma::row_major> bf[4];
#pragma unroll
            for (int ii = 0; ii < 2; ii++)
                wmma::load_matrix_sync(af[ii], as + (wm * 32 + ii * 16) * AS_LD + kk * 16, AS_LD);
#pragma unroll
            for (int j = 0; j < 4; j++)
                wmma::load_matrix_sync(bf[j], bs + (kk * 16) * BS_LD + wn * 64 + j * 16, BS_LD);
#pragma unroll
            for (int ii = 0; ii < 2; ii++)
#pragma unroll
                for (int j = 0; j < 4; j++)
                    wmma::mma_sync(acc[ii][j], af[ii], bf[j], acc[ii][j]);
        }
        __syncthreads();
    }

    if (MODE == 0) {
        float* C = (float*)Cv;
#pragma unroll
        for (int i = 0; i < 2; i++)
#pragma unroll
            for (int j = 0; j < 4; j++) {
                float* dst = C + (size_t)(row0 + wm * 32 + i * 16) * N
                               + col0 + wn * 64 + j * 16;
                wmma::store_matrix_sync(dst, acc[i][j], N, wmma::mem_row_major);
            }
    } else {
        float* Cs = smf + warp * 320;
        int rr = lane >> 1, cc = (lane & 1) * 8;
#pragma unroll
        for (int i = 0; i < 2; i++) {
#pragma unroll
            for (int j = 0; j < 4; j++) {
                wmma::store_matrix_sync(Cs, acc[i][j], 20, wmma::mem_row_major);
                __syncwarp();
                int r = row0 + wm * 32 + i * 16 + rr;
                int c0l = col0 + wn * 64 + j * 16 + cc;
#pragma unroll
                for (int e = 0; e < 8; e++) {
                    int c = c0l + e;
                    if (c < N) {
                        float vv = Cs[rr * 20 + cc + e];
                        if (MODE == 1 || MODE == 2) vv += bias[c];
                        if (MODE == 2)
                            vv = 0.5f * vv * (1.0f + erff(vv * 0.70710678118654752f));
                        if (MODE == 1)
                            ((float*)Cv)[(size_t)r * N + c] = vv;
                        else
                            ((__half*)Cv)[(size_t)r * N + c] = H16(vv);
                    }
                }
                __syncwarp();
            }
        }
    }
}

template <int MODE>
__global__ void __launch_bounds__(256, 2)
gemm_h_kernel(const __half* __restrict__ A, const __half* __restrict__ Bt,
              const float* __restrict__ bias, void* __restrict__ Cv,
              int N, int K, int ldB) {
    gemm_body<MODE>(A, Bt, bias, Cv, N, K, K, ldB, 0);
}

// Split-K=2: blockIdx.z picks K-half; writes fp32 partial slab z.
__global__ void __launch_bounds__(256, 2)
gemm_h_splitk(const __half* __restrict__ A, const __half* __restrict__ Bt,
              float* __restrict__ C, int N, int K, int ldB) {
    int z = blockIdx.z;
    int kh = K >> 1;
    gemm_body<0>(A, Bt, nullptr, (void*)(C + (size_t)z * Tq * Dq),
                 N, kh, K, ldB, z * kh);
}

// Batched QKV: blockIdx.z selects weight + output slab; outputs half
__global__ void __launch_bounds__(256, 2)
gemm_qkv_kernel(const __half* __restrict__ A, const __half* __restrict__ w0,
                const __half* __restrict__ w1, const __half* __restrict__ w2,
                __half* __restrict__ c0) {
    const __half* Bm = (blockIdx.z == 0) ? w0 : (blockIdx.z == 1) ? w1 : w2;
    __half* C = c0 + (size_t)blockIdx.z * Tq * Dq;
    gemm_body<3>(A, Bm, nullptr, (void*)C, Dq, Dq, Dq, Dq, 0);
}

// ---------------------------------------------------------------------------
// Fully fused attention: scores (fp16 MMA) -> softmax (fp32) -> write probs
// -> P·V (fp16 MMA) -> write O (half). grid (S/32, B*H), 256 threads.
// Smem: Qs[32][72]h | Ks[64][72]h (reused for V) | Sc[32][520]f | Ph[32][520]h
// ---------------------------------------------------------------------------
#define ATTQ_HALFS (32 * 72)
#define ATTK_HALFS (64 * 72)
#define SC_LD 520
#define PH_OFF_BYTES ((ATTQ_HALFS + ATTK_HALFS) * 2 + 32 * SC_LD * 4)
#define ATT_SMEM_BYTES (PH_OFF_BYTES + 32 * SC_LD * 2)

__global__ void __launch_bounds__(256)
attn_fused(const __half* __restrict__ q, const __half* __restrict__ k,
           const __half* __restrict__ v, const int* __restrict__ mask,
           float* __restrict__ probs, __half* __restrict__ o) {
    extern __shared__ char asmraw[];
    __half* Qs = (__half*)asmraw;                                   // [32][72]
    __half* Ks = Qs + ATTQ_HALFS;                                   // [64][72]
    float* Sc = (float*)(asmraw + (ATTQ_HALFS + ATTK_HALFS) * 2);   // [32][520]
    __half* Ph = (__half*)(asmraw + PH_OFF_BYTES);                  // [32][520]

    int bh = blockIdx.y;
    int b = bh / Hq, h = bh % Hq;
    int q0 = blockIdx.x * 32;
    int tid = threadIdx.x;
    int warp = tid >> 5, lane = tid & 31;

    // ---- Phase 1: scores = Q K^T ----
    {
        int r = tid >> 3, c = tid & 7;
        *(uint4*)(Qs + r * 72 + c * 8) =
            *(const uint4*)(q + (size_t)(b * Sq + q0 + r) * Dq + h * HDq + c * 8);
    }
    int wm2 = warp & 1, wn4 = warp >> 1;   // 2 m x 4 n
    for (int kt = 0; kt < 8; kt++) {
        __syncthreads();
#pragma unroll
        for (int i = 0; i < 2; i++) {
            int idx = tid + i * 256;
            int r = idx >> 3, c = idx & 7;
            *(uint4*)(Ks + r * 72 + c * 8) =
                *(const uint4*)(k + (size_t)(b * Sq + kt * 64 + r) * Dq + h * HDq + c * 8);
        }
        __syncthreads();

        wmma::fragment<wmma::accumulator, 16, 16, 16, float> acc;
        wmma::fill_fragment(acc, 0.0f);
#pragma unroll
        for (int kk = 0; kk < 4; kk++) {
            wmma::fragment<wmma::matrix_a, 16, 16, 16, __half, wmma::row_major> af;
            wmma::fragment<wmma::matrix_b, 16, 16, 16, __half, wmma::col_major> bf;
            wmma::load_matrix_sync(af, Qs + (wm2 * 16) * 72 + kk * 16, 72);
            wmma::load_matrix_sync(bf, Ks + (wn4 * 16) * 72 + kk * 16, 72);
            wmma::mma_sync(acc, af, bf, acc);
        }
        wmma::store_matrix_sync(Sc + (wm2 * 16) * SC_LD + kt * 64 + wn4 * 16,
                                acc, SC_LD, wmma::mem_row_major);
    }
    __syncthreads();

    // ---- Phase 2: softmax; write probs (fp32) + keep half copy in Ph ----
    const float scale = 0.03608439182435161f;  // 1/sqrt(D=768)
#pragma unroll
    for (int i = 0; i < 4; i++) {
        int r = warp * 4 + i;
        float vv[16];
        float m = -INFINITY;
#pragma unroll
        for (int j = 0; j < 16; j++) {
            int col = lane + j * 32;
            float f = Sc[r * SC_LD + col] * scale;
            if (mask[b * Sq + col] == 0) f = -INFINITY;
            vv[j] = f;
            m = fmaxf(m, f);
        }
#pragma unroll
        for (int oo = 16; oo > 0; oo >>= 1) m = fmaxf(m, __shfl_xor_sync(0xffffffffu, m, oo));
        float s = 0.f;
#pragma unroll
        for (int j = 0; j < 16; j++) {
            vv[j] = __expf(vv[j] - m);
            s += vv[j];
        }
#pragma unroll
        for (int oo = 16; oo > 0; oo >>= 1) s += __shfl_xor_sync(0xffffffffu, s, oo);
        float inv = 1.0f / s;
        float* dst = probs + ((size_t)bh * Sq + q0 + r) * Sq;
#pragma unroll
        for (int j = 0; j < 16; j++) {
            float pv = vv[j] * inv;
            dst[lane + j * 32] = pv;
            Ph[r * SC_LD + lane + j * 32] = H16(pv);
        }
    }
    __syncthreads();

    // ---- Phase 3: O = P V (accumulate across 8 V-tiles of 64 keys) ----
    // 8 warps -> 2x4 grid of 16x16 output frags covering [32, 64]
    wmma::fragment<wmma::accumulator, 16, 16, 16, float> oacc;
    wmma::fill_fragment(oacc, 0.0f);
    for (int kt = 0; kt < 8; kt++) {
        __syncthreads();
#pragma unroll
        for (int i = 0; i < 2; i++) {
            int idx = tid + i * 256;
            int r = idx >> 3, c = idx & 7;
            *(uint4*)(Ks + r * 72 + c * 8) =
                *(const uint4*)(v + (size_t)(b * Sq + kt * 64 + r) * Dq + h * HDq + c * 8);
        }
        __syncthreads();
#pragma unroll
        for (int kk = 0; kk < 4; kk++) {
            wmma::fragment<wmma::matrix_a, 16, 16, 16, __half, wmma::row_major> af;
            wmma::fragment<wmma::matrix_b, 16, 16, 16, __half, wmma::row_major> bf;
            wmma::load_matrix_sync(af, Ph + (wm2 * 16) * SC_LD + kt * 64 + kk * 16, SC_LD);
            wmma::load_matrix_sync(bf, Ks + (kk * 16) * 72 + wn4 * 16, 72);
            wmma::mma_sync(oacc, af, bf, oacc);
        }
    }
    __syncthreads();

    // stage via Sc (free now), convert to half, write O
    float* Cs = Sc + warp * 320;  // [16][20]
    wmma::store_matrix_sync(Cs, oacc, 20, wmma::mem_row_major);
    __syncwarp();
    int rr = lane >> 1, cc = (lane & 1) * 8;
    int qr = q0 + wm2 * 16 + rr;
    int dc = h * HDq + wn4 * 16 + cc;
    __half* dst = o + (size_t)(b * Sq + qr) * Dq + dc;
#pragma unroll
    for (int e = 0; e < 8; e++) dst[e] = H16(Cs[rr * 20 + cc + e]);
}

// ---------------------------------------------------------------------------
// Host orchestration (graph-capturable: kernel launches only)
// ---------------------------------------------------------------------------
extern "C" void kernel_launch(void* const* d_in, const int* in_sizes, int n_in,
                              void* d_out, int out_size) {
    const int*   ids  = (const int*)d_in[0];
    const int*   mask = (const int*)d_in[1];
    const float* wemb = (const float*)d_in[2];
    const float* pemb = (const float*)d_in[3];
    const float* semb = (const float*)d_in[4];
    const float* elng = (const float*)d_in[5];
    const float* elnb = (const float*)d_in[6];
    const float* Wq   = (const float*)d_in[7];
    const float* Wk   = (const float*)d_in[8];
    const float* Wv   = (const float*)d_in[9];
    const float* Wo   = (const float*)d_in[10];
    const float* f1w  = (const float*)d_in[11];
    const float* f1b  = (const float*)d_in[12];
    const float* f2w  = (const float*)d_in[13];
    const float* f2b  = (const float*)d_in[14];
    const float* l1g  = (const float*)d_in[15];
    const float* l1b  = (const float*)d_in[16];
    const float* l2g  = (const float*)d_in[17];
    const float* l2b  = (const float*)d_in[18];
    const float* outw = (const float*)d_in[19];
    const float* outb = (const float*)d_in[20];

    static bool attr_done = false;
    if (!attr_done) {
        cudaFuncSetAttribute(gemm_h_kernel<0>, cudaFuncAttributeMaxDynamicSharedMemorySize, GEMM_SMEM_BYTES);
        cudaFuncSetAttribute(gemm_h_kernel<1>, cudaFuncAttributeMaxDynamicSharedMemorySize, GEMM_SMEM_BYTES);
        cudaFuncSetAttribute(gemm_h_kernel<2>, cudaFuncAttributeMaxDynamicSharedMemorySize, GEMM_SMEM_BYTES);
        cudaFuncSetAttribute(gemm_h_kernel<3>, cudaFuncAttributeMaxDynamicSharedMemorySize, GEMM_SMEM_BYTES);
        cudaFuncSetAttribute(gemm_h_splitk,    cudaFuncAttributeMaxDynamicSharedMemorySize, GEMM_SMEM_BYTES);
        cudaFuncSetAttribute(gemm_qkv_kernel,  cudaFuncAttributeMaxDynamicSharedMemorySize, GEMM_SMEM_BYTES);
        cudaFuncSetAttribute(attn_fused,       cudaFuncAttributeMaxDynamicSharedMemorySize, ATT_SMEM_BYTES);
        attr_done = true;
    }

    float* ws = nullptr;
    cudaGetSymbolAddress((void**)&ws, g_ws);
    __half* hws = nullptr;
    cudaGetSymbolAddress((void**)&hws, g_hws);

    float* x     = ws;
    float* x1    = x  + (size_t)Tq * Dq;
    float* tmp32 = x1 + (size_t)Tq * Dq;            // 2 slabs
    float* bpad  = tmp32 + 2 * (size_t)Tq * Dq;

    __half* xH   = hws;
    __half* x1H  = xH  + (size_t)Tq * Dq;
    __half* qH   = x1H + (size_t)Tq * Dq;
    __half* kH   = qH  + (size_t)Tq * Dq;
    __half* vH   = kH  + (size_t)Tq * Dq;
    __half* tbH  = vH  + (size_t)Tq * Dq;
    __half* hbH  = tbH + (size_t)Tq * Dq;
    __half* wpadH = hbH + (size_t)Tq * Fq;
    __half* hWq  = wpadH + (size_t)Dq * Npad;
    __half* hWk  = hWq + LDD;
    __half* hWv  = hWk + LDD;
    __half* hWo  = hWv + LDD;
    __half* hF1  = hWo + LDD;
    __half* hF2  = hF1 + LDF;

    float* logits = (float*)d_out;                       // [B*S, V]
    float* attn   = logits + (size_t)Tq * Vq;            // [L, B*H, S, S]

    // ---- pre-round weights to fp16 + pad vocab ----
    {
        size_t n4dd = LDD / 4;
        unsigned gdd = (unsigned)((n4dd + 255) / 256);
        cvt_half_kernel<<<gdd, 256>>>(Wq, hWq, n4dd);
        cvt_half_kernel<<<gdd, 256>>>(Wk, hWk, n4dd);
        cvt_half_kernel<<<gdd, 256>>>(Wv, hWv, n4dd);
        cvt_half_kernel<<<gdd, 256>>>(Wo, hWo, n4dd);
        size_t n4df = LDF / 4;
        unsigned gdf = (unsigned)((n4df + 255) / 256);
        cvt_half_kernel<<<gdf, 256>>>(f1w, hF1, n4df);
        cvt_half_kernel<<<gdf, 256>>>(f2w, hF2, n4df);
        size_t n4v = ((size_t)Dq * Npad) / 4;
        pad_vocab_kernel<<<(unsigned)((n4v + 255) / 256), 256>>>(outw, wpadH);
        pad_bias_kernel<<<(Npad + 255) / 256, 256>>>(outb, bpad);
    }

    embed_ln_kernel<<<Tq, 256>>>(ids, wemb, pemb, semb, elng, elnb, x, xH);

    for (int l = 0; l < Lq; l++) {
        float* slab = attn + (size_t)l * Bq * Hq * Sq * Sq;
        dim3 gDD(Dq / 128, Tq / 128);  // (6,16)

        gemm_qkv_kernel<<<dim3(Dq / 128, Tq / 128, 3), 256, GEMM_SMEM_BYTES>>>(
            xH, hWq + (size_t)l * Dq * Dq, hWk + (size_t)l * Dq * Dq,
            hWv + (size_t)l * Dq * Dq, qH);

        attn_fused<<<dim3(Sq / 32, Bq * Hq), 256, ATT_SMEM_BYTES>>>(
            qH, kH, vH, mask, slab, tbH);

        gemm_h_splitk<<<dim3(Dq / 128, Tq / 128, 2), 256, GEMM_SMEM_BYTES>>>(
            tbH, hWo + (size_t)l * Dq * Dq, tmp32, Dq, Dq, Dq);
        add_ln3_kernel<<<Tq, 256>>>(x, tmp32, tmp32 + (size_t)Tq * Dq, nullptr,
                                    l1g + (size_t)l * Dq, l1b + (size_t)l * Dq, x1, x1H);

        gemm_h_kernel<2><<<dim3(Fq / 128, Tq / 128), 256, GEMM_SMEM_BYTES>>>(
            x1H, hF1 + (size_t)l * Dq * Fq, f1b + (size_t)l * Fq, hbH, Fq, Dq, Fq);
        gemm_h_splitk<<<dim3(Dq / 128, Tq / 128, 2), 256, GEMM_SMEM_BYTES>>>(
            hbH, hF2 + (size_t)l * Fq * Dq, tmp32, Dq, Fq, Dq);
        add_ln3_kernel<<<Tq, 256>>>(x1, tmp32, tmp32 + (size_t)Tq * Dq,
                                    f2b + (size_t)l * Dq,
                                    l2g + (size_t)l * Dq, l2b + (size_t)l * Dq, x, xH);
    }

    gemm_h_kernel<1><<<dim3(Npad / 128, Tq / 128), 256, GEMM_SMEM_BYTES>>>(
        xH, wpadH, bpad, logits, Vq, Dq, Npad);
}

// round 16
// speedup vs baseline: 1.0007x; 1.0007x over previous
#include <cuda_runtime.h>
#include <mma.h>
#include <math.h>
#include <cstdint>
#include <cuda_fp16.h>

using namespace nvcuda;

// BERT-base forward: B=4, S=512, L=12, D=768, H=12, F=3072, V=30522
#define Bq 4
#define Sq 512
#define Lq 12
#define Dq 768
#define Hq 12
#define Fq 3072
#define Vq 30522
#define HDq 64
#define Tq 2048    // B*S tokens
#define Npad 30592 // 239*128, padded vocab width

#define LDD ((size_t)Lq * Dq * Dq)
#define LDF ((size_t)Lq * Dq * Fq)

// fp32 workspace: x, x1 [T,D]; tmp32 [2][T,D]; bpad [Npad]
__device__ float g_ws[4 * (size_t)Tq * Dq + Npad];
// fp16 workspace: xH,x1H,qH,kH,vH,tbH [T,D]; hbH [T,F]; wpadH [D,Npad];
// hWq,hWk,hWv,hWo [L,D,D]; hF1 [L,D,F]; hF2 [L,F,D]
__device__ __half g_hws[6 * (size_t)Tq * Dq + (size_t)Tq * Fq
                        + (size_t)Dq * Npad + 4 * LDD + 2 * LDF];

__device__ __forceinline__ __half H16(float x) { return __float2half_rn(x); }

__device__ __forceinline__ void cp16(uint32_t dst, const void* src) {
    asm volatile("cp.async.cg.shared.global [%0], [%1], 16;" :: "r"(dst), "l"(src));
}
__device__ __forceinline__ void cp_commit() {
    asm volatile("cp.async.commit_group;");
}
template <int N>
__device__ __forceinline__ void cp_wait() {
    asm volatile("cp.async.wait_group %0;" :: "n"(N));
}
__device__ __forceinline__ uint32_t smem_u32(const void* p) {
    return (uint32_t)__cvta_generic_to_shared(p);
}

// ---------------------------------------------------------------------------
// Block-wide sum of (a,b) pairs, 256 threads
// ---------------------------------------------------------------------------
__device__ __forceinline__ float2 blockReduce2(float a, float b) {
#pragma unroll
    for (int o = 16; o > 0; o >>= 1) {
        a += __shfl_down_sync(0xffffffffu, a, o);
        b += __shfl_down_sync(0xffffffffu, b, o);
    }
    __shared__ float2 sh[8];
    int lane = threadIdx.x & 31, wid = threadIdx.x >> 5;
    if (lane == 0) sh[wid] = make_float2(a, b);
    __syncthreads();
    if (wid == 0) {
        float2 v = (lane < 8) ? sh[lane] : make_float2(0.f, 0.f);
#pragma unroll
        for (int o = 4; o > 0; o >>= 1) {
            v.x += __shfl_down_sync(0xffffffffu, v.x, o);
            v.y += __shfl_down_sync(0xffffffffu, v.y, o);
        }
        if (lane == 0) sh[0] = v;
    }
    __syncthreads();
    return sh[0];
}

// ---------------------------------------------------------------------------
// Embedding + LayerNorm: fp32 out + fp16-rounded copy
// ---------------------------------------------------------------------------
__global__ void embed_ln_kernel(const int* __restrict__ ids,
                                const float* __restrict__ wemb,
                                const float* __restrict__ pemb,
                                const float* __restrict__ semb,
                                const float* __restrict__ g,
                                const float* __restrict__ bta,
                                float* __restrict__ x,
                                __half* __restrict__ xH) {
    int t = blockIdx.x;
    int s = t & (Sq - 1);
    int id = ids[t];
    float v[3];
    float sum = 0.f, sq = 0.f;
#pragma unroll
    for (int i = 0; i < 3; i++) {
        int d = threadIdx.x + i * 256;
        float val = wemb[(size_t)id * Dq + d] + pemb[(size_t)s * Dq + d] + semb[d];
        v[i] = val;
        sum += val;
        sq += val * val;
    }
    float2 r = blockReduce2(sum, sq);
    float mu = r.x * (1.0f / Dq);
    float var = r.y * (1.0f / Dq) - mu * mu;
    float rstd = rsqrtf(var + 1e-5f);
#pragma unroll
    for (int i = 0; i < 3; i++) {
        int d = threadIdx.x + i * 256;
        float o = (v[i] - mu) * rstd * g[d] + bta[d];
        x[(size_t)t * Dq + d] = o;
        xH[(size_t)t * Dq + d] = H16(o);
    }
}

// ---------------------------------------------------------------------------
// out = LayerNorm(a + b0 + b1 + bias?): fp32 out + fp16 copy (split-K merge)
// ---------------------------------------------------------------------------
__global__ void add_ln3_kernel(const float* __restrict__ a,
                               const float* __restrict__ b0,
                               const float* __restrict__ b1,
                               const float* __restrict__ bias,
                               const float* __restrict__ g,
                               const float* __restrict__ bta,
                               float* __restrict__ out,
                               __half* __restrict__ outH) {
    int t = blockIdx.x;
    float v[3];
    float sum = 0.f, sq = 0.f;
#pragma unroll
    for (int i = 0; i < 3; i++) {
        int d = threadIdx.x + i * 256;
        size_t idx = (size_t)t * Dq + d;
        float val = a[idx] + b0[idx] + b1[idx];
        if (bias) val += bias[d];
        v[i] = val;
        sum += val;
        sq += val * val;
    }
    float2 r = blockReduce2(sum, sq);
    float mu = r.x * (1.0f / Dq);
    float var = r.y * (1.0f / Dq) - mu * mu;
    float rstd = rsqrtf(var + 1e-5f);
#pragma unroll
    for (int i = 0; i < 3; i++) {
        int d = threadIdx.x + i * 256;
        float o = (v[i] - mu) * rstd * g[d] + bta[d];
        out[(size_t)t * Dq + d] = o;
        outH[(size_t)t * Dq + d] = H16(o);
    }
}

// ---------------------------------------------------------------------------
// Elementwise fp32 -> fp16 (RNE), n multiple of 4
// ---------------------------------------------------------------------------
__global__ void cvt_half_kernel(const float* __restrict__ in,
                                __half* __restrict__ out, size_t n4) {
    size_t i = (size_t)blockIdx.x * 256 + threadIdx.x;
    if (i >= n4) return;
    float4 v = ((const float4*)in)[i];
    ((__half2*)out)[i * 2 + 0] = __floats2half2_rn(v.x, v.y);
    ((__half2*)out)[i * 2 + 1] = __floats2half2_rn(v.z, v.w);
}

__global__ void pad_vocab_kernel(const float* __restrict__ w,
                                 __half* __restrict__ wp) {
    size_t gid = (size_t)blockIdx.x * 256 + threadIdx.x;
    size_t i4 = gid * 4;
    if (i4 >= (size_t)Dq * Npad) return;
    int k = (int)(i4 / Npad);
    int c = (int)(i4 % Npad);
    float a = (c + 0 < Vq) ? w[(size_t)k * Vq + c + 0] : 0.f;
    float b = (c + 1 < Vq) ? w[(size_t)k * Vq + c + 1] : 0.f;
    float d = (c + 2 < Vq) ? w[(size_t)k * Vq + c + 2] : 0.f;
    float e = (c + 3 < Vq) ? w[(size_t)k * Vq + c + 3] : 0.f;
    ((__half2*)wp)[gid * 2 + 0] = __floats2half2_rn(a, b);
    ((__half2*)wp)[gid * 2 + 1] = __floats2half2_rn(d, e);
}

__global__ void pad_bias_kernel(const float* __restrict__ b,
                                float* __restrict__ bp) {
    int c = blockIdx.x * 256 + threadIdx.x;
    if (c < Npad) bp[c] = (c < Vq) ? b[c] : 0.f;
}

// ---------------------------------------------------------------------------
// FP16 WMMA GEMM, cp.async 4-stage: C[M,N] = A[M, kOff:kOff+Klen] @ B slice.
// 128x128 tile, BK=32, 8 warps (4 M x 2 N), warp tile 32x64, fp32 accum.
// MODE: 0 = float out, plain (direct frag store)
//       1 = float out, +bias (staged)
//       2 = half out, +bias + exact GELU (staged)
//       3 = half out, plain (staged)
// ---------------------------------------------------------------------------
#define AS_LD 40
#define BS_LD 136
#define STAGE_HALFS (128 * AS_LD + 32 * BS_LD)        // 9472
#define GEMM_SMEM_BYTES (4 * STAGE_HALFS * 2)         // 75776

template <int MODE>
__device__ __forceinline__ void gemm_body(const __half* __restrict__ A,
                                          const __half* __restrict__ Bt,
                                          const float* __restrict__ bias,
                                          void* __restrict__ Cv,
                                          int N, int Klen, int ldA, int ldB,
                                          int kOff) {
    extern __shared__ char smraw[];
    __half* smh = (__half*)smraw;
    float* smf = (float*)smraw;
    uint32_t smb = smem_u32(smraw);

    int tid = threadIdx.x;
    int row0 = blockIdx.y * 128, col0 = blockIdx.x * 128;
    int warp = tid >> 5, lane = tid & 31;
    int wm = warp & 3, wn = warp >> 2;

    wmma::fragment<wmma::accumulator, 16, 16, 16, float> acc[2][4];
#pragma unroll
    for (int i = 0; i < 2; i++)
#pragma unroll
        for (int j = 0; j < 4; j++)
            wmma::fill_fragment(acc[i][j], 0.0f);

    auto issue = [&](int i) {
        uint32_t sb = smb + (uint32_t)((i & 3) * STAGE_HALFS) * 2;
        uint32_t bb = sb + 128 * AS_LD * 2;
        int k0 = kOff + (i << 5);
#pragma unroll
        for (int it = 0; it < 2; it++) {
            int idx = tid + it * 256;
            int r = idx >> 2, c = idx & 3;
            cp16(sb + (uint32_t)((r * AS_LD + c * 8) * 2),
                 A + (size_t)(row0 + r) * ldA + k0 + c * 8);
        }
#pragma unroll
        for (int it = 0; it < 2; it++) {
            int idx = tid + it * 256;
            int r = idx >> 4, c = idx & 15;
            cp16(bb + (uint32_t)((r * BS_LD + c * 8) * 2),
                 Bt + (size_t)(k0 + r) * ldB + col0 + c * 8);
        }
        cp_commit();
    };

    int niter = Klen >> 5;
    issue(0);
    if (niter > 1) issue(1);
    if (niter > 2) issue(2);

    for (int i = 0; i < niter; i++) {
        if (i + 3 < niter) {
            issue(i + 3);
            cp_wait<3>();
        } else if (i + 2 < niter) {
            cp_wait<2>();
        } else if (i + 1 < niter) {
            cp_wait<1>();
        } else {
            cp_wait<0>();
        }
        __syncthreads();

        const __half* as = smh + (i & 3) * STAGE_HALFS;
        const __half* bs = as + 128 * AS_LD;
#pragma unroll
        for (int kk = 0; kk < 2; kk++) {
            wmma::fragment<wmma::matrix_a, 16, 16, 16, __half, wmma::row_major> af[2];
            wmma::fragment<wmma::matrix_b, 16, 16, 16, __half, wmma::row_major> bf[4];
#pragma unroll
            for (int ii = 0; ii < 2; ii++)
                wmma::load_matrix_sync(af[ii], as + (wm * 32 + ii * 16) * AS_LD + kk * 16, AS_LD);
#pragma unroll
            for (int j = 0; j < 4; j++)
                wmma::load_matrix_sync(bf[j], bs + (kk * 16) * BS_LD + wn * 64 + j * 16, BS_LD);
#pragma unroll
            for (int ii = 0; ii < 2; ii++)
#pragma unroll
                for (int j = 0; j < 4; j++)
                    wmma::mma_sync(acc[ii][j], af[ii], bf[j], acc[ii][j]);
        }
        __syncthreads();
    }

    if (MODE == 0) {
        float* C = (float*)Cv;
#pragma unroll
        for (int i = 0; i < 2; i++)
#pragma unroll
            for (int j = 0; j < 4; j++) {
                float* dst = C + (size_t)(row0 + wm * 32 + i * 16) * N
                               + col0 + wn * 64 + j * 16;
                wmma::store_matrix_sync(dst, acc[i][j], N, wmma::mem_row_major);
            }
    } else {
        float* Cs = smf + warp * 320;
        int rr = lane >> 1, cc = (lane & 1) * 8;
#pragma unroll
        for (int i = 0; i < 2; i++) {
#pragma unroll
            for (int j = 0; j < 4; j++) {
                wmma::store_matrix_sync(Cs, acc[i][j], 20, wmma::mem_row_major);
                __syncwarp();
                int r = row0 + wm * 32 + i * 16 + rr;
                int c0l = col0 + wn * 64 + j * 16 + cc;
#pragma unroll
                for (int e = 0; e < 8; e++) {
                    int c = c0l + e;
                    if (c < N) {
                        float vv = Cs[rr * 20 + cc + e];
                        if (MODE == 1 || MODE == 2) vv += bias[c];
                        if (MODE == 2)
                            vv = 0.5f * vv * (1.0f + erff(vv * 0.70710678118654752f));
                        if (MODE == 1)
                            ((float*)Cv)[(size_t)r * N + c] = vv;
                        else
                            ((__half*)Cv)[(size_t)r * N + c] = H16(vv);
                    }
                }
                __syncwarp();
            }
        }
    }
}

template <int MODE>
__global__ void __launch_bounds__(256, 2)
gemm_h_kernel(const __half* __restrict__ A, const __half* __restrict__ Bt,
              const float* __restrict__ bias, void* __restrict__ Cv,
              int N, int K, int ldB) {
    gemm_body<MODE>(A, Bt, bias, Cv, N, K, K, ldB, 0);
}

// Split-K=2: blockIdx.z picks K-half; writes fp32 partial slab z.
__global__ void __launch_bounds__(256, 2)
gemm_h_splitk(const __half* __restrict__ A, const __half* __restrict__ Bt,
              float* __restrict__ C, int N, int K, int ldB) {
    int z = blockIdx.z;
    int kh = K >> 1;
    gemm_body<0>(A, Bt, nullptr, (void*)(C + (size_t)z * Tq * Dq),
                 N, kh, K, ldB, z * kh);
}

// Batched QKV: blockIdx.z selects weight + output slab; outputs half
__global__ void __launch_bounds__(256, 2)
gemm_qkv_kernel(const __half* __restrict__ A, const __half* __restrict__ w0,
                const __half* __restrict__ w1, const __half* __restrict__ w2,
                __half* __restrict__ c0) {
    const __half* Bm = (blockIdx.z == 0) ? w0 : (blockIdx.z == 1) ? w1 : w2;
    __half* C = c0 + (size_t)blockIdx.z * Tq * Dq;
    gemm_body<3>(A, Bm, nullptr, (void*)C, Dq, Dq, Dq, Dq, 0);
}

// ---------------------------------------------------------------------------
// Fully fused attention: scores (fp16 MMA) -> softmax (fp32) -> write probs
// -> P·V (fp16 MMA) -> write O (half). grid (S/32, B*H), 256 threads.
// Smem: Qs[32][72]h | Ks[64][72]h (reused for V) | Sc[32][520]f | Ph[32][520]h
// ---------------------------------------------------------------------------
#define ATTQ_HALFS (32 * 72)
#define ATTK_HALFS (64 * 72)
#define SC_LD 520
#define PH_OFF_BYTES ((ATTQ_HALFS + ATTK_HALFS) * 2 + 32 * SC_LD * 4)
#define ATT_SMEM_BYTES (PH_OFF_BYTES + 32 * SC_LD * 2)

__global__ void __launch_bounds__(256)
attn_fused(const __half* __restrict__ q, const __half* __restrict__ k,
           const __half* __restrict__ v, const int* __restrict__ mask,
           float* __restrict__ probs, __half* __restrict__ o) {
    extern __shared__ char asmraw[];
    __half* Qs = (__half*)asmraw;                                   // [32][72]
    __half* Ks = Qs + ATTQ_HALFS;                                   // [64][72]
    float* Sc = (float*)(asmraw + (ATTQ_HALFS + ATTK_HALFS) * 2);   // [32][520]
    __half* Ph = (__half*)(asmraw + PH_OFF_BYTES);                  // [32][520]

    int bh = blockIdx.y;
    int b = bh / Hq, h = bh % Hq;
    int q0 = blockIdx.x * 32;
    int tid = threadIdx.x;
    int warp = tid >> 5, lane = tid & 31;

    // ---- Phase 1: scores = Q K^T ----
    {
        int r = tid >> 3, c = tid & 7;
        *(uint4*)(Qs + r * 72 + c * 8) =
            *(const uint4*)(q + (size_t)(b * Sq + q0 + r) * Dq + h * HDq + c * 8);
    }
    int wm2 = warp & 1, wn4 = warp >> 1;   // 2 m x 4 n
    for (int kt = 0; kt < 8; kt++) {
        __syncthreads();
#pragma unroll
        for (int i = 0; i < 2; i++) {
            int idx = tid + i * 256;
            int r = idx >> 3, c = idx & 7;
            *(uint4*)(Ks + r * 72 + c * 8) =
                *(const uint4*)(k + (size_t)(b * Sq + kt * 64 + r) * Dq + h * HDq + c * 8);
        }
        __syncthreads();

        wmma::fragment<wmma::accumulator, 16, 16, 16, float> acc;
        wmma::fill_fragment(acc, 0.0f);
#pragma unroll
        for (int kk = 0; kk < 4; kk++) {
            wmma::fragment<wmma::matrix_a, 16, 16, 16, __half, wmma::row_major> af;
            wmma::fragment<wmma::matrix_b, 16, 16, 16, __half, wmma::col_major> bf;
            wmma::load_matrix_sync(af, Qs + (wm2 * 16) * 72 + kk * 16, 72);
            wmma::load_matrix_sync(bf, Ks + (wn4 * 16) * 72 + kk * 16, 72);
            wmma::mma_sync(acc, af, bf, acc);
        }
        wmma::store_matrix_sync(Sc + (wm2 * 16) * SC_LD + kt * 64 + wn4 * 16,
                                acc, SC_LD, wmma::mem_row_major);
    }
    __syncthreads();

    // ---- Phase 2: softmax; write probs (fp32) + keep half copy in Ph ----
    const float scale = 0.03608439182435161f;  // 1/sqrt(D=768)
#pragma unroll
    for (int i = 0; i < 4; i++) {
        int r = warp * 4 + i;
        float vv[16];
        float m = -INFINITY;
#pragma unroll
        for (int j = 0; j < 16; j++) {
            int col = lane + j * 32;
            float f = Sc[r * SC_LD + col] * scale;
            if (mask[b * Sq + col] == 0) f = -INFINITY;
            vv[j] = f;
            m = fmaxf(m, f);
        }
#pragma unroll
        for (int oo = 16; oo > 0; oo >>= 1) m = fmaxf(m, __shfl_xor_sync(0xffffffffu, m, oo));
        float s = 0.f;
#pragma unroll
        for (int j = 0; j < 16; j++) {
            vv[j] = __expf(vv[j] - m);
            s += vv[j];
        }
#pragma unroll
        for (int oo = 16; oo > 0; oo >>= 1) s += __shfl_xor_sync(0xffffffffu, s, oo);
        float inv = 1.0f / s;
        float* dst = probs + ((size_t)bh * Sq + q0 + r) * Sq;
#pragma unroll
        for (int j = 0; j < 16; j++) {
            float pv = vv[j] * inv;
            dst[lane + j * 32] = pv;
            Ph[r * SC_LD + lane + j * 32] = H16(pv);
        }
    }
    __syncthreads();

    // ---- Phase 3: O = P V (accumulate across 8 V-tiles of 64 keys) ----
    // 8 warps -> 2x4 grid of 16x16 output frags covering [32, 64]
    wmma::fragment<wmma::accumulator, 16, 16, 16, float> oacc;
    wmma::fill_fragment(oacc, 0.0f);
    for (int kt = 0; kt < 8; kt++) {
        __syncthreads();
#pragma unroll
        for (int i = 0; i < 2; i++) {
            int idx = tid + i * 256;
            int r = idx >> 3, c = idx & 7;
            *(uint4*)(Ks + r * 72 + c * 8) =
                *(const uint4*)(v + (size_t)(b * Sq + kt * 64 + r) * Dq + h * HDq + c * 8);
        }
        __syncthreads();
#pragma unroll
        for (int kk = 0; kk < 4; kk++) {
            wmma::fragment<wmma::matrix_a, 16, 16, 16, __half, wmma::row_major> af;
            wmma::fragment<wmma::matrix_b, 16, 16, 16, __half, wmma::row_major> bf;
            wmma::load_matrix_sync(af, Ph + (wm2 * 16) * SC_LD + kt * 64 + kk * 16, SC_LD);
            wmma::load_matrix_sync(bf, Ks + (kk * 16) * 72 + wn4 * 16, 72);
            wmma::mma_sync(oacc, af, bf, oacc);
        }
    }
    __syncthreads();

    // stage via Sc (free now), convert to half, write O
    float* Cs = Sc + warp * 320;  // [16][20]
    wmma::store_matrix_sync(Cs, oacc, 20, wmma::mem_row_major);
    __syncwarp();
    int rr = lane >> 1, cc = (lane & 1) * 8;
    int qr = q0 + wm2 * 16 + rr;
    int dc = h * HDq + wn4 * 16 + cc;
    __half* dst = o + (size_t)(b * Sq + qr) * Dq + dc;
#pragma unroll
    for (int e = 0; e < 8; e++) dst[e] = H16(Cs[rr * 20 + cc + e]);
}

// ---------------------------------------------------------------------------
// Host orchestration (graph-capturable: kernel launches only)
// ---------------------------------------------------------------------------
extern "C" void kernel_launch(void* const* d_in, const int* in_sizes, int n_in,
                              void* d_out, int out_size) {
    const int*   ids  = (const int*)d_in[0];
    const int*   mask = (const int*)d_in[1];
    const float* wemb = (const float*)d_in[2];
    const float* pemb = (const float*)d_in[3];
    const float* semb = (const float*)d_in[4];
    const float* elng = (const float*)d_in[5];
    const float* elnb = (const float*)d_in[6];
    const float* Wq   = (const float*)d_in[7];
    const float* Wk   = (const float*)d_in[8];
    const float* Wv   = (const float*)d_in[9];
    const float* Wo   = (const float*)d_in[10];
    const float* f1w  = (const float*)d_in[11];
    const float* f1b  = (const float*)d_in[12];
    const float* f2w  = (const float*)d_in[13];
    const float* f2b  = (const float*)d_in[14];
    const float* l1g  = (const float*)d_in[15];
    const float* l1b  = (const float*)d_in[16];
    const float* l2g  = (const float*)d_in[17];
    const float* l2b  = (const float*)d_in[18];
    const float* outw = (const float*)d_in[19];
    const float* outb = (const float*)d_in[20];

    static bool attr_done = false;
    if (!attr_done) {
        cudaFuncSetAttribute(gemm_h_kernel<0>, cudaFuncAttributeMaxDynamicSharedMemorySize, GEMM_SMEM_BYTES);
        cudaFuncSetAttribute(gemm_h_kernel<1>, cudaFuncAttributeMaxDynamicSharedMemorySize, GEMM_SMEM_BYTES);
        cudaFuncSetAttribute(gemm_h_kernel<2>, cudaFuncAttributeMaxDynamicSharedMemorySize, GEMM_SMEM_BYTES);
        cudaFuncSetAttribute(gemm_h_kernel<3>, cudaFuncAttributeMaxDynamicSharedMemorySize, GEMM_SMEM_BYTES);
        cudaFuncSetAttribute(gemm_h_splitk,    cudaFuncAttributeMaxDynamicSharedMemorySize, GEMM_SMEM_BYTES);
        cudaFuncSetAttribute(gemm_qkv_kernel,  cudaFuncAttributeMaxDynamicSharedMemorySize, GEMM_SMEM_BYTES);
        cudaFuncSetAttribute(attn_fused,       cudaFuncAttributeMaxDynamicSharedMemorySize, ATT_SMEM_BYTES);
        attr_done = true;
    }

    float* ws = nullptr;
    cudaGetSymbolAddress((void**)&ws, g_ws);
    __half* hws = nullptr;
    cudaGetSymbolAddress((void**)&hws, g_hws);

    float* x     = ws;
    float* x1    = x  + (size_t)Tq * Dq;
    float* tmp32 = x1 + (size_t)Tq * Dq;            // 2 slabs
    float* bpad  = tmp32 + 2 * (size_t)Tq * Dq;

    __half* xH   = hws;
    __half* x1H  = xH  + (size_t)Tq * Dq;
    __half* qH   = x1H + (size_t)Tq * Dq;
    __half* kH   = qH  + (size_t)Tq * Dq;
    __half* vH   = kH  + (size_t)Tq * Dq;
    __half* tbH  = vH  + (size_t)Tq * Dq;
    __half* hbH  = tbH + (size_t)Tq * Dq;
    __half* wpadH = hbH + (size_t)Tq * Fq;
    __half* hWq  = wpadH + (size_t)Dq * Npad;
    __half* hWk  = hWq + LDD;
    __half* hWv  = hWk + LDD;
    __half* hWo  = hWv + LDD;
    __half* hF1  = hWo + LDD;
    __half* hF2  = hF1 + LDF;

    float* logits = (float*)d_out;                       // [B*S, V]
    float* attn   = logits + (size_t)Tq * Vq;            // [L, B*H, S, S]

    // ---- pre-round weights to fp16 + pad vocab ----
    {
        size_t n4dd = LDD / 4;
        unsigned gdd = (unsigned)((n4dd + 255) / 256);
        cvt_half_kernel<<<gdd, 256>>>(Wq, hWq, n4dd);
        cvt_half_kernel<<<gdd, 256>>>(Wk, hWk, n4dd);
        cvt_half_kernel<<<gdd, 256>>>(Wv, hWv, n4dd);
        cvt_half_kernel<<<gdd, 256>>>(Wo, hWo, n4dd);
        size_t n4df = LDF / 4;
        unsigned gdf = (unsigned)((n4df + 255) / 256);
        cvt_half_kernel<<<gdf, 256>>>(f1w, hF1, n4df);
        cvt_half_kernel<<<gdf, 256>>>(f2w, hF2, n4df);
        size_t n4v = ((size_t)Dq * Npad) / 4;
        pad_vocab_kernel<<<(unsigned)((n4v + 255) / 256), 256>>>(outw, wpadH);
        pad_bias_kernel<<<(Npad + 255) / 256, 256>>>(outb, bpad);
    }

    embed_ln_kernel<<<Tq, 256>>>(ids, wemb, pemb, semb, elng, elnb, x, xH);

    for (int l = 0; l < Lq; l++) {
        float* slab = attn + (size_t)l * Bq * Hq * Sq * Sq;
        dim3 gDD(Dq / 128, Tq / 128);  // (6,16)

        gemm_qkv_kernel<<<dim3(Dq / 128, Tq / 128, 3), 256, GEMM_SMEM_BYTES>>>(
            xH, hWq + (size_t)l * Dq * Dq, hWk + (size_t)l * Dq * Dq,
            hWv + (size_t)l * Dq * Dq, qH);

        attn_fused<<<dim3(Sq / 32, Bq * Hq), 256, ATT_SMEM_BYTES>>>(
            qH, kH, vH, mask, slab, tbH);

        gemm_h_splitk<<<dim3(Dq / 128, Tq / 128, 2), 256, GEMM_SMEM_BYTES>>>(
            tbH, hWo + (size_t)l * Dq * Dq, tmp32, Dq, Dq, Dq);
        add_ln3_kernel<<<Tq, 256>>>(x, tmp32, tmp32 + (size_t)Tq * Dq, nullptr,
                                    l1g + (size_t)l * Dq, l1b + (size_t)l * Dq, x1, x1H);

        gemm_h_kernel<2><<<dim3(Fq / 128, Tq / 128), 256, GEMM_SMEM_BYTES>>>(
            x1H, hF1 + (size_t)l * Dq * Fq, f1b + (size_t)l * Fq, hbH, Fq, Dq, Fq);
        gemm_h_splitk<<<dim3(Dq / 128, Tq / 128, 2), 256, GEMM_SMEM_BYTES>>>(
            hbH, hF2 + (size_t)l * Fq * Dq, tmp32, Dq, Fq, Dq);
        add_ln3_kernel<<<Tq, 256>>>(x1, tmp32, tmp32 + (size_t)Tq * Dq,
                                    f2b + (size_t)l * Dq,
                                    l2g + (size_t)l * Dq, l2b + (size_t)l * Dq, x, xH);
    }

    gemm_h_kernel<1><<<dim3(Npad / 128, Tq / 128), 256, GEMM_SMEM_BYTES>>>(
        xH, wpadH, bpad, logits, Vq, Dq, Npad);
}